// round 14
// baseline (speedup 1.0000x reference)
#include <cuda_runtime.h>
#include <math.h>
#include <stdint.h>

// Problem constants
#define NROWS 32768   // B*H*W
#define DDIM  64
#define MCODE 1024
#define HWSZ  1024
#define ZQ_ELEMS 2097152

// Static device scratch
__device__ float g_key[2 * NROWS];       // per code-half: min key (y2 - 2*dot)
__device__ float g_kidx[2 * NROWS];      // per code-half: argmin index (as float)
__device__ unsigned long long g_lacc = 0ull;  // fixed-point sum of s^2 (scale 2^22)
__device__ int   g_ctr = 0;              // zq completion counter (self-resetting)

// ---------------------------------------------------------------------------
// helpers
// ---------------------------------------------------------------------------
__device__ __forceinline__ uint32_t f2tf32(float a) {
    uint32_t r; asm("cvt.rna.tf32.f32 %0, %1;" : "=r"(r) : "f"(a)); return r;
}
// D = A(16x8) * B(8x8) + C, tf32, fp32 accum
__device__ __forceinline__ void mma16n8k8(float* c, uint32_t a0, uint32_t a1,
                                          uint32_t a2, uint32_t a3,
                                          uint32_t b0, uint32_t b1) {
    asm volatile(
        "mma.sync.aligned.m16n8k8.row.col.f32.tf32.tf32.f32 "
        "{%0,%1,%2,%3}, {%4,%5,%6,%7}, {%8,%9}, {%0,%1,%2,%3};"
        : "+f"(c[0]), "+f"(c[1]), "+f"(c[2]), "+f"(c[3])
        : "r"(a0), "r"(a1), "r"(a2), "r"(a3), "r"(b0), "r"(b1));
}

// Pack one (code bc, kstep bs) pair of float4s into the hi/lo tf32 fragment
// smem layout (row stride 257 uint4 to spread store banks), and accumulate
// the code's y2 via a deterministic 8-lane tree (lanes = bs groups).
__device__ __forceinline__ void pack_chunk(uint4* bdst, float* y2dst,
                                           int bc, int bs, float4 fa, float4 fb) {
    float v0[4] = {fa.x, fa.y, fa.z, fa.w};
    float v1[4] = {fb.x, fb.y, fb.z, fb.w};
    float part = 0.f;
    #pragma unroll
    for (int t = 0; t < 4; ++t) {
        uint32_t h0 = f2tf32(v0[t]), h1 = f2tf32(v1[t]);
        uint32_t l0 = f2tf32(v0[t] - __uint_as_float(h0));
        uint32_t l1 = f2tf32(v1[t] - __uint_as_float(h1));
        bdst[bs * 257 + bc * 4 + t] = make_uint4(h0, h1, l0, l1);
        part += v0[t] * v0[t] + v1[t] * v1[t];
    }
    part += __shfl_down_sync(0xffffffffu, part, 4, 8);
    part += __shfl_down_sync(0xffffffffu, part, 2, 8);
    part += __shfl_down_sync(0xffffffffu, part, 1, 8);
    if (bs == 0) y2dst[bc] = part;
}

// ---------------------------------------------------------------------------
// Kernel 1: 3xTF32 mma.sync distance GEMM + fused argmin + in-CTA codebook
// packing. Grid 148 = 74 uneven row blocks (12x416 + 62x448 rows) x 2 code
// halves -> one CTA per SM, no stranded SMs. 512 threads = 16 warps x 32
// rows; warps beyond the block's row count skip MMA/epilogue (rows are
// 32-aligned so warps are fully active or fully idle). One sync per chunk:
// pack chunk ch+1 into buf^1 BEFORE the MMA on buf.
// smem: y2c[2][64] | A2 float2[8][512][4] (128KB) | Bpack 2 x 8*257 uint4.
// ---------------------------------------------------------------------------
#define SM_Y2   0
#define SM_A    1024
#define SM_B    132096
#define BBUF_U4 2056                     // 8 * 257 uint4 per buffer (32896 B)
#define GEMM_SMEM (132096 + 2 * 32896)   // 197888

__global__ __launch_bounds__(512, 1)
void gemm_argmin_kernel(const float* __restrict__ z, const float* __restrict__ cb) {
    extern __shared__ char sm[];
    float*  y2c   = (float*)(sm + SM_Y2);
    float2* A2    = (float2*)(sm + SM_A);
    uint4*  Bpack = (uint4*)(sm + SM_B);
    int tid = threadIdx.x;
    int wid = tid >> 5, lane = tid & 31;
    int g = lane >> 2, tt = lane & 3;
    int half = blockIdx.x & 1;
    int bi = blockIdx.x >> 1;            // 0..73
    int r0, rows;
    if (bi < 12) { r0 = bi * 416;               rows = 416; }
    else         { r0 = 4992 + (bi - 12) * 448; rows = 448; }
    int w32 = wid * 32;
    bool active = (w32 < rows);
    const float* cbh = cb + (size_t)half * 512 * DDIM;
    int bc = tid >> 3;                   // code within chunk (0..63)
    int bs = tid & 7;                    // k-step (0..7)

    // prologue: LDG raw B chunk 0 (coalesced: 8 threads cover one code row)
    float4 c0 = *(const float4*)&cbh[(size_t)bc * DDIM + bs * 8];
    float4 c1 = *(const float4*)&cbh[(size_t)bc * DDIM + bs * 8 + 4];

    // A prep: per-row (b,hw) addressing (blocks may cross batch boundaries)
    {
        int roff = lane >> 2, tp = lane & 3;
        #pragma unroll
        for (int p = 0; p < 4; ++p) {
            int r = p * 128 + wid * 8 + roff;
            if (r < rows) {
                int n = r0 + r;
                const float* zp = z + (size_t)(n >> 10) * 65536 + (n & 1023);
                #pragma unroll
                for (int s = 0; s < 8; ++s) {
                    float v0 = zp[(s * 8 + tp) * 1024];
                    float v1 = zp[(s * 8 + tp + 4) * 1024];
                    A2[(s * 512 + r) * 4 + tp] = make_float2(v0, v1);
                }
            }
        }
    }

    // pack chunk 0 into buffer 0
    pack_chunk(Bpack, y2c, bc, bs, c0, c1);
    __syncthreads();

    // preload raw chunk 1
    if (1) {
        const float* src = &cbh[(size_t)(64 + bc) * DDIM + bs * 8];
        c0 = *(const float4*)src;
        c1 = *(const float4*)(src + 4);
    }

    float best[4];
    int   bidx[4];
    #pragma unroll
    for (int i = 0; i < 4; ++i) { best[i] = 3.4028235e38f; bidx[i] = 0; }

    for (int ch = 0; ch < 8; ++ch) {
        int buf = ch & 1;
        // pack chunk ch+1 into buf^1 (its last readers synced at end of ch-1)
        if (ch < 7)
            pack_chunk(Bpack + (buf ^ 1) * BBUF_U4, y2c + (buf ^ 1) * 64,
                       bc, bs, c0, c1);
        // prefetch raw chunk ch+2 (LDG latency hidden under the MMA below)
        if (ch < 6) {
            const float* src = &cbh[(size_t)((ch + 2) * 64 + bc) * DDIM + bs * 8];
            c0 = *(const float4*)src;
            c1 = *(const float4*)(src + 4);
        }

        if (active) {
            const uint4* Bb  = Bpack + buf * BBUF_U4;
            const float* y2b = y2c + buf * 64;

            float acc[2][8][4];
            #pragma unroll
            for (int m = 0; m < 2; ++m)
                #pragma unroll
                for (int j = 0; j < 8; ++j)
                    #pragma unroll
                    for (int e = 0; e < 4; ++e) acc[m][j][e] = 0.f;

            #pragma unroll
            for (int s = 0; s < 8; ++s) {
                float2 f0 = A2[(s * 512 + w32 + g) * 4 + tt];
                float2 f1 = A2[(s * 512 + w32 + 8 + g) * 4 + tt];
                float2 f2 = A2[(s * 512 + w32 + 16 + g) * 4 + tt];
                float2 f3 = A2[(s * 512 + w32 + 24 + g) * 4 + tt];
                uint32_t h0x = f2tf32(f0.x), h0y = f2tf32(f0.y);
                uint32_t h1x = f2tf32(f1.x), h1y = f2tf32(f1.y);
                uint32_t h2x = f2tf32(f2.x), h2y = f2tf32(f2.y);
                uint32_t h3x = f2tf32(f3.x), h3y = f2tf32(f3.y);
                uint32_t l0x = f2tf32(f0.x - __uint_as_float(h0x));
                uint32_t l0y = f2tf32(f0.y - __uint_as_float(h0y));
                uint32_t l1x = f2tf32(f1.x - __uint_as_float(h1x));
                uint32_t l1y = f2tf32(f1.y - __uint_as_float(h1y));
                uint32_t l2x = f2tf32(f2.x - __uint_as_float(h2x));
                uint32_t l2y = f2tf32(f2.y - __uint_as_float(h2y));
                uint32_t l3x = f2tf32(f3.x - __uint_as_float(h3x));
                uint32_t l3y = f2tf32(f3.y - __uint_as_float(h3y));
                #pragma unroll
                for (int j = 0; j < 8; ++j) {
                    uint4 bq = Bb[s * 257 + (j * 8 + g) * 4 + tt];
                    mma16n8k8(acc[0][j], h0x, h1x, h0y, h1y, bq.x, bq.y);  // hi*hi
                    mma16n8k8(acc[0][j], h0x, h1x, h0y, h1y, bq.z, bq.w);  // hi*lo
                    mma16n8k8(acc[0][j], l0x, l1x, l0y, l1y, bq.x, bq.y);  // lo*hi
                    mma16n8k8(acc[1][j], h2x, h3x, h2y, h3y, bq.x, bq.y);
                    mma16n8k8(acc[1][j], h2x, h3x, h2y, h3y, bq.z, bq.w);
                    mma16n8k8(acc[1][j], l2x, l3x, l2y, l3y, bq.x, bq.y);
                }
            }

            // epilogue: key = y2 - 2*dot, running argmin (first-occurrence ties)
            #pragma unroll
            for (int j = 0; j < 8; ++j) {
                int cl = ch * 64 + j * 8 + 2 * tt;
                float2 y = *(const float2*)&y2b[j * 8 + 2 * tt];
                float k0 = fmaf(acc[0][j][0], -2.0f, y.x);
                float k1 = fmaf(acc[0][j][1], -2.0f, y.y);
                float k2 = fmaf(acc[0][j][2], -2.0f, y.x);
                float k3 = fmaf(acc[0][j][3], -2.0f, y.y);
                float k4 = fmaf(acc[1][j][0], -2.0f, y.x);
                float k5 = fmaf(acc[1][j][1], -2.0f, y.y);
                float k6 = fmaf(acc[1][j][2], -2.0f, y.x);
                float k7 = fmaf(acc[1][j][3], -2.0f, y.y);
                if (k0 < best[0]) { best[0] = k0; bidx[0] = cl; }
                if (k1 < best[0]) { best[0] = k1; bidx[0] = cl + 1; }
                if (k2 < best[1]) { best[1] = k2; bidx[1] = cl; }
                if (k3 < best[1]) { best[1] = k3; bidx[1] = cl + 1; }
                if (k4 < best[2]) { best[2] = k4; bidx[2] = cl; }
                if (k5 < best[2]) { best[2] = k5; bidx[2] = cl + 1; }
                if (k6 < best[3]) { best[3] = k6; bidx[3] = cl; }
                if (k7 < best[3]) { best[3] = k7; bidx[3] = cl + 1; }
            }
        }

        __syncthreads();   // pack(ch+1) visible; all reads of buf complete
    }

    // cross-lane (t-group) argmin reduce; lane with tt==0 owns the row
    if (active) {
        #pragma unroll
        for (int m = 0; m < 4; ++m) {
            float v = best[m];
            int id = bidx[m];
            #pragma unroll
            for (int d = 1; d < 4; d <<= 1) {
                float v2 = __shfl_xor_sync(0xffffffffu, v, d);
                int   i2 = __shfl_xor_sync(0xffffffffu, id, d);
                if (v2 < v || (v2 == v && i2 < id)) { v = v2; id = i2; }
            }
            if (tt == 0) {
                int row = r0 + w32 + (m >> 1) * 16 + (m & 1) * 8 + g;
                g_key[half * NROWS + row] = v;
                g_kidx[half * NROWS + row] = (float)(half * 512 + id);
            }
        }
    }
}

// ---------------------------------------------------------------------------
// Kernel 2: z_q, output transpose, ind merge + deterministic fixed-point
// loss accumulation. Last CTA finalizes + resets counters. (Unchanged.)
// ---------------------------------------------------------------------------
__global__ __launch_bounds__(256)
void zq_kernel(const float* __restrict__ z,
               const float* __restrict__ noise,
               float* __restrict__ out,
               float* __restrict__ out_ind,
               float* __restrict__ out_loss) {
    __shared__ float zt[64][33];     // z[b, d, hw0+w] tile
    __shared__ float zq[32 * 65];
    __shared__ float sred[256];
    int t = threadIdx.x;
    int c = blockIdx.x;
    int b = c >> 5;
    int p = c & 31;
    int r0 = b * 1024 + p * 32;

    int row = t >> 3;
    int seg = t & 7;
    int n = r0 + row;

    // hoisted independent loads (issue before the tile barrier)
    float4 n0 = *(const float4*)&noise[n * 64 + seg * 8];
    float4 n1 = *(const float4*)&noise[n * 64 + seg * 8 + 4];
    float k0 = g_key[n], k1 = g_key[NROWS + n];
    float i0 = g_kidx[n], i1 = g_kidx[NROWS + n];

    // load z tile: 64 d x 32 hw, coalesced over hw
    {
        const float* zb = z + (size_t)b * 65536 + p * 32;
        int w = t & 31, db = t >> 5;
        #pragma unroll
        for (int it = 0; it < 8; ++it) {
            int d = it * 8 + db;
            zt[d][w] = zb[d * 1024 + w];
        }
    }
    __syncthreads();

    float nv[8] = {n0.x, n0.y, n0.z, n0.w, n1.x, n1.y, n1.z, n1.w};
    float zv[8];
    #pragma unroll
    for (int i = 0; i < 8; ++i) zv[i] = zt[seg * 8 + i][row];

    float s = 0.f, xs = 0.f;
    #pragma unroll
    for (int i = 0; i < 8; ++i) { s += nv[i] * nv[i]; xs += zv[i] * zv[i]; }
    s += __shfl_down_sync(0xffffffffu, s, 4, 8);
    xs += __shfl_down_sync(0xffffffffu, xs, 4, 8);
    s += __shfl_down_sync(0xffffffffu, s, 2, 8);
    xs += __shfl_down_sync(0xffffffffu, xs, 2, 8);
    s += __shfl_down_sync(0xffffffffu, s, 1, 8);
    xs += __shfl_down_sync(0xffffffffu, xs, 1, 8);
    float norm2 = __shfl_sync(0xffffffffu, s, 0, 8);
    float x2 = __shfl_sync(0xffffffffu, xs, 0, 8);

    // merge the two code-half candidates (half0 wins ties: lower idx)
    float mk, mi;
    if (k1 < k0) { mk = k1; mi = i1; }
    else         { mk = k0; mi = i0; }
    if (seg == 0) out_ind[n] = mi;

    float dmin = x2 + mk;
    float scale = sqrtf(fmaxf(dmin, 0.f)) / fmaxf(sqrtf(norm2), 1e-9f);

    float part = 0.f;
    #pragma unroll
    for (int i = 0; i < 8; ++i) {
        float q = zv[i] + nv[i] * scale;
        part += q;
        zq[row * 65 + seg * 8 + i] = q;
    }
    sred[t] = part;
    __syncthreads();

    // two independent 128-thread tree reductions (rows 0-15 | rows 16-31)
    for (int off = 64; off > 0; off >>= 1) {
        if ((t & 127) < off) sred[t] += sred[t + off];
        __syncthreads();
    }
    // deterministic fixed-point accumulation of s^2 (scale 2^22)
    if ((t & 127) == 0) {
        float sv = sred[t];
        unsigned long long q =
            (unsigned long long)__double2ll_rn((double)sv * (double)sv * 4194304.0);
        atomicAdd(&g_lacc, q);
    }

    // write out transposed: out[b*65536 + dd*1024 + p*32 + r]
    {
        int dd = t >> 2;
        int rg = t & 3;
        float4 o0, o1;
        o0.x = zq[(rg * 8 + 0) * 65 + dd];
        o0.y = zq[(rg * 8 + 1) * 65 + dd];
        o0.z = zq[(rg * 8 + 2) * 65 + dd];
        o0.w = zq[(rg * 8 + 3) * 65 + dd];
        o1.x = zq[(rg * 8 + 4) * 65 + dd];
        o1.y = zq[(rg * 8 + 5) * 65 + dd];
        o1.z = zq[(rg * 8 + 6) * 65 + dd];
        o1.w = zq[(rg * 8 + 7) * 65 + dd];
        float* op = out + (size_t)b * 65536 + dd * 1024 + p * 32 + rg * 8;
        *(float4*)op = o0;
        *(float4*)(op + 4) = o1;
    }

    // completion protocol: single-thread fence orders this CTA's lacc adds
    __syncthreads();
    if (t == 0) {
        __threadfence();
        int v = atomicAdd(&g_ctr, 1);
        if (v == (int)gridDim.x - 1) {
            unsigned long long tot = atomicAdd(&g_lacc, 0ull);
            *out_loss = (float)((double)tot * (1.0 / 4194304.0) * (1.0 / 33554432.0));
            g_lacc = 0ull;   // reset for next graph replay
            g_ctr = 0;
        }
    }
}

// ---------------------------------------------------------------------------
extern "C" void kernel_launch(void* const* d_in, const int* in_sizes, int n_in,
                              void* d_out, int out_size) {
    const float* z     = (const float*)d_in[0];
    const float* cb    = (const float*)d_in[1];
    const float* noise = (const float*)d_in[2];
    float* out      = (float*)d_out;
    float* out_loss = out + ZQ_ELEMS;
    float* out_ind  = out + ZQ_ELEMS + 1;

    cudaFuncSetAttribute(gemm_argmin_kernel,
                         cudaFuncAttributeMaxDynamicSharedMemorySize, GEMM_SMEM);

    gemm_argmin_kernel<<<148, 512, GEMM_SMEM>>>(z, cb);
    zq_kernel<<<1024, 256>>>(z, noise, out, out_ind, out_loss);
}

// round 15
// speedup vs baseline: 1.0617x; 1.0617x over previous
#include <cuda_runtime.h>
#include <math.h>
#include <stdint.h>

// Problem constants
#define NROWS 32768   // B*H*W
#define DDIM  64
#define MCODE 1024
#define HWSZ  1024
#define ZQ_ELEMS 2097152

// Static device scratch
__device__ float g_key[2 * NROWS];       // per code-half: min key (y2 - 2*dot)
__device__ float g_kidx[2 * NROWS];      // per code-half: argmin index (as float)
__device__ float g_y2[MCODE];
__device__ unsigned long long g_lacc = 0ull;  // fixed-point sum of s^2 (scale 2^22)
__device__ int   g_ctr = 0;              // zq completion counter (self-resetting)
// Codebook packed in mma-fragment order: [chunk(16)][s(8)][ci(64)][t(4)] uint4
//   uint4 = { tf32hi(k0+t), tf32hi(k0+t+4), tf32lo(k0+t), tf32lo(k0+t+4) }
__device__ uint4 g_bpack[16 * 2048];

// ---------------------------------------------------------------------------
// helpers
// ---------------------------------------------------------------------------
__device__ __forceinline__ uint32_t f2tf32(float a) {
    uint32_t r; asm("cvt.rna.tf32.f32 %0, %1;" : "=r"(r) : "f"(a)); return r;
}
__device__ __forceinline__ uint32_t smem_u32(const void* p) {
    uint32_t a;
    asm("{ .reg .u64 t; cvta.to.shared.u64 t, %1; cvt.u32.u64 %0, t; }"
        : "=r"(a) : "l"(p));
    return a;
}
__device__ __forceinline__ void bulk_g2s(uint32_t dst, const void* src,
                                         uint32_t bytes, uint32_t mbar) {
    asm volatile(
        "cp.async.bulk.shared::cta.global.mbarrier::complete_tx::bytes [%0], [%1], %2, [%3];"
        :: "r"(dst), "l"(src), "r"(bytes), "r"(mbar) : "memory");
}
__device__ __forceinline__ void mbar_init(uint32_t mbar, uint32_t cnt) {
    asm volatile("mbarrier.init.shared.b64 [%0], %1;" :: "r"(mbar), "r"(cnt) : "memory");
}
__device__ __forceinline__ void mbar_expect_tx(uint32_t mbar, uint32_t bytes) {
    asm volatile("mbarrier.arrive.expect_tx.shared.b64 _, [%0], %1;"
                 :: "r"(mbar), "r"(bytes) : "memory");
}
__device__ __forceinline__ void mbar_wait(uint32_t mbar, uint32_t parity) {
    uint32_t done;
    asm volatile(
        "{\n\t.reg .pred p;\n\t"
        "mbarrier.try_wait.parity.acquire.cta.shared::cta.b64 p, [%1], %2;\n\t"
        "selp.b32 %0, 1, 0, p;\n\t}"
        : "=r"(done) : "r"(mbar), "r"(parity) : "memory");
    while (!done) {
        asm volatile(
            "{\n\t.reg .pred p;\n\t"
            "mbarrier.try_wait.parity.acquire.cta.shared::cta.b64 p, [%1], %2, 0x989680;\n\t"
            "selp.b32 %0, 1, 0, p;\n\t}"
            : "=r"(done) : "r"(mbar), "r"(parity) : "memory");
    }
}
// D = A(16x8) * B(8x8) + C, tf32, fp32 accum
__device__ __forceinline__ void mma16n8k8(float* c, uint32_t a0, uint32_t a1,
                                          uint32_t a2, uint32_t a3,
                                          uint32_t b0, uint32_t b1) {
    asm volatile(
        "mma.sync.aligned.m16n8k8.row.col.f32.tf32.tf32.f32 "
        "{%0,%1,%2,%3}, {%4,%5,%6,%7}, {%8,%9}, {%0,%1,%2,%3};"
        : "+f"(c[0]), "+f"(c[1]), "+f"(c[2]), "+f"(c[3])
        : "r"(a0), "r"(a1), "r"(a2), "r"(a3), "r"(b0), "r"(b1));
}

// ---------------------------------------------------------------------------
// Kernel 1: pack codebook into tf32 hi/lo fragment order + per-code y2.
// (Unchanged from the 80.4us R8 kernel.)
// ---------------------------------------------------------------------------
__global__ void bprep_kernel(const float* __restrict__ cb) {
    int g = blockIdx.x * 256 + threadIdx.x;
    int c = g >> 5, s = (g >> 2) & 7, t = g & 3;
    float v0 = cb[c * DDIM + s * 8 + t];
    float v1 = cb[c * DDIM + s * 8 + t + 4];
    uint32_t h0 = f2tf32(v0), h1 = f2tf32(v1);
    uint32_t l0 = f2tf32(v0 - __uint_as_float(h0));
    uint32_t l1 = f2tf32(v1 - __uint_as_float(h1));
    int chunk = c >> 6, ci = c & 63;
    g_bpack[chunk * 2048 + ci * 4 + s * 256 + t] = make_uint4(h0, h1, l0, l1);
    float y = v0 * v0 + v1 * v1;
    #pragma unroll
    for (int d = 16; d > 0; d >>= 1)
        y += __shfl_xor_sync(0xffffffffu, y, d);
    if ((threadIdx.x & 31) == 0) g_y2[c] = y;
}

// ---------------------------------------------------------------------------
// Kernel 2: 3xTF32 mma.sync distance GEMM + fused argmin.
// ONLY CHANGE vs the 80.4us R8 kernel: grid 148 = 74 uneven row blocks
// (12x416 + 62x448 rows) x 2 code halves -> one CTA per SM, no stranded SMs.
// Warps past the block's row count skip MMA/epilogue (rows 32-aligned).
// Everything else (B pipeline, syncs, epilogue, numerics) is identical.
// ---------------------------------------------------------------------------
#define SM_MB   0
#define SM_Y2   128
#define SM_A    2176
#define SM_B    133248
#define GEMM_SMEM 198784

__global__ __launch_bounds__(512, 1)
void gemm_argmin_kernel(const float* __restrict__ z) {
    extern __shared__ char sm[];
    uint32_t sb = smem_u32(sm);
    float2* A2 = (float2*)(sm + SM_A);
    const float* y2s = (const float*)(sm + SM_Y2);
    int tid = threadIdx.x;
    int wid = tid >> 5, lane = tid & 31;
    int g = lane >> 2, tt = lane & 3;
    int half = blockIdx.x & 1;
    int bi = blockIdx.x >> 1;            // 0..73
    int r0, rows;
    if (bi < 12) { r0 = bi * 416;               rows = 416; }
    else         { r0 = 4992 + (bi - 12) * 448; rows = 448; }
    int w32 = wid * 32;
    bool active = (w32 < rows);
    const uint4* bsrc = g_bpack + half * 8 * 2048;

    if (tid == 0) {
        mbar_init(sb + SM_MB + 0, 1);
        mbar_init(sb + SM_MB + 8, 1);
    }
    __syncthreads();  // make mbar init visible before bulk ops

    // kick off B chunks 0 and 1
    if (tid == 0) {
        mbar_expect_tx(sb + SM_MB + 0, 32768);
        bulk_g2s(sb + SM_B, bsrc, 32768, sb + SM_MB + 0);
        mbar_expect_tx(sb + SM_MB + 8, 32768);
        bulk_g2s(sb + SM_B + 32768, bsrc + 2048, 32768, sb + SM_MB + 8);
    }

    // A prep: per-row (b,hw) addressing (blocks may cross batch boundaries)
    {
        int roff = lane >> 2, tp = lane & 3;
        #pragma unroll
        for (int p = 0; p < 4; ++p) {
            int r = p * 128 + wid * 8 + roff;
            if (r < rows) {
                int n = r0 + r;
                const float* zp = z + (size_t)(n >> 10) * 65536 + (n & 1023);
                #pragma unroll
                for (int s = 0; s < 8; ++s) {
                    float v0 = zp[(s * 8 + tp) * 1024];
                    float v1 = zp[(s * 8 + tp + 4) * 1024];
                    A2[(s * 512 + r) * 4 + tp] = make_float2(v0, v1);
                }
            }
        }
    }
    for (int i = tid; i < 512; i += 512)
        ((float*)(sm + SM_Y2))[i] = g_y2[half * 512 + i];
    __syncthreads();

    float best[4];
    int   bidx[4];
    #pragma unroll
    for (int i = 0; i < 4; ++i) { best[i] = 3.4028235e38f; bidx[i] = 0; }

    for (int ch = 0; ch < 8; ++ch) {
        int buf = ch & 1;
        mbar_wait(sb + SM_MB + buf * 8, (ch >> 1) & 1);

        if (active) {
            const uint4* Bb = (const uint4*)(sm + SM_B + buf * 32768);

            float acc[2][8][4];
            #pragma unroll
            for (int m = 0; m < 2; ++m)
                #pragma unroll
                for (int j = 0; j < 8; ++j)
                    #pragma unroll
                    for (int e = 0; e < 4; ++e) acc[m][j][e] = 0.f;

            #pragma unroll
            for (int s = 0; s < 8; ++s) {
                float2 f0 = A2[(s * 512 + w32 + g) * 4 + tt];
                float2 f1 = A2[(s * 512 + w32 + 8 + g) * 4 + tt];
                float2 f2 = A2[(s * 512 + w32 + 16 + g) * 4 + tt];
                float2 f3 = A2[(s * 512 + w32 + 24 + g) * 4 + tt];
                uint32_t h0x = f2tf32(f0.x), h0y = f2tf32(f0.y);
                uint32_t h1x = f2tf32(f1.x), h1y = f2tf32(f1.y);
                uint32_t h2x = f2tf32(f2.x), h2y = f2tf32(f2.y);
                uint32_t h3x = f2tf32(f3.x), h3y = f2tf32(f3.y);
                uint32_t l0x = f2tf32(f0.x - __uint_as_float(h0x));
                uint32_t l0y = f2tf32(f0.y - __uint_as_float(h0y));
                uint32_t l1x = f2tf32(f1.x - __uint_as_float(h1x));
                uint32_t l1y = f2tf32(f1.y - __uint_as_float(h1y));
                uint32_t l2x = f2tf32(f2.x - __uint_as_float(h2x));
                uint32_t l2y = f2tf32(f2.y - __uint_as_float(h2y));
                uint32_t l3x = f2tf32(f3.x - __uint_as_float(h3x));
                uint32_t l3y = f2tf32(f3.y - __uint_as_float(h3y));
                #pragma unroll
                for (int j = 0; j < 8; ++j) {
                    uint4 bq = Bb[s * 256 + (j * 8 + g) * 4 + tt];
                    mma16n8k8(acc[0][j], h0x, h1x, h0y, h1y, bq.x, bq.y);  // hi*hi
                    mma16n8k8(acc[0][j], h0x, h1x, h0y, h1y, bq.z, bq.w);  // hi*lo
                    mma16n8k8(acc[0][j], l0x, l1x, l0y, l1y, bq.x, bq.y);  // lo*hi
                    mma16n8k8(acc[1][j], h2x, h3x, h2y, h3y, bq.x, bq.y);
                    mma16n8k8(acc[1][j], h2x, h3x, h2y, h3y, bq.z, bq.w);
                    mma16n8k8(acc[1][j], l2x, l3x, l2y, l3y, bq.x, bq.y);
                }
            }

            // epilogue: key = y2 - 2*dot, running argmin (first-occurrence ties)
            #pragma unroll
            for (int j = 0; j < 8; ++j) {
                int cl = ch * 64 + j * 8 + 2 * tt;
                float2 y = ((const float2*)y2s)[cl >> 1];
                #pragma unroll
                for (int m = 0; m < 2; ++m) {
                    float k0 = fmaf(acc[m][j][0], -2.0f, y.x);
                    float k1 = fmaf(acc[m][j][1], -2.0f, y.y);
                    float k2 = fmaf(acc[m][j][2], -2.0f, y.x);
                    float k3 = fmaf(acc[m][j][3], -2.0f, y.y);
                    if (k0 < best[m * 2 + 0]) { best[m * 2 + 0] = k0; bidx[m * 2 + 0] = cl; }
                    if (k1 < best[m * 2 + 0]) { best[m * 2 + 0] = k1; bidx[m * 2 + 0] = cl + 1; }
                    if (k2 < best[m * 2 + 1]) { best[m * 2 + 1] = k2; bidx[m * 2 + 1] = cl; }
                    if (k3 < best[m * 2 + 1]) { best[m * 2 + 1] = k3; bidx[m * 2 + 1] = cl + 1; }
                }
            }
        }

        __syncthreads();  // everyone done with buf before refill
        if (ch + 2 < 8 && tid == 0) {
            mbar_expect_tx(sb + SM_MB + buf * 8, 32768);
            bulk_g2s(sb + SM_B + buf * 32768, bsrc + (ch + 2) * 2048, 32768,
                     sb + SM_MB + buf * 8);
        }
    }

    // cross-lane (t-group) argmin reduce; lane with tt==0 owns the row
    if (active) {
        #pragma unroll
        for (int m = 0; m < 4; ++m) {
            float v = best[m];
            int id = bidx[m];
            #pragma unroll
            for (int d = 1; d < 4; d <<= 1) {
                float v2 = __shfl_xor_sync(0xffffffffu, v, d);
                int   i2 = __shfl_xor_sync(0xffffffffu, id, d);
                if (v2 < v || (v2 == v && i2 < id)) { v = v2; id = i2; }
            }
            if (tt == 0) {
                int row = r0 + w32 + (m >> 1) * 16 + (m & 1) * 8 + g;
                g_key[half * NROWS + row] = v;
                g_kidx[half * NROWS + row] = (float)(half * 512 + id);
            }
        }
    }
}

// ---------------------------------------------------------------------------
// Kernel 3: z_q, output transpose, ind merge + deterministic fixed-point
// loss accumulation (int64 atomics). Last CTA finalizes + resets counters.
// (Byte-identical to the 80.4us R8 kernel.)
// ---------------------------------------------------------------------------
__global__ __launch_bounds__(256)
void zq_kernel(const float* __restrict__ z,
               const float* __restrict__ noise,
               float* __restrict__ out,
               float* __restrict__ out_ind,
               float* __restrict__ out_loss) {
    __shared__ float zt[64][33];     // z[b, d, hw0+w] tile
    __shared__ float zq[32 * 65];
    __shared__ float sred[256];
    int t = threadIdx.x;
    int c = blockIdx.x;
    int b = c >> 5;
    int p = c & 31;
    int r0 = b * 1024 + p * 32;

    int row = t >> 3;
    int seg = t & 7;
    int n = r0 + row;

    // hoisted independent loads (issue before the tile barrier)
    float4 n0 = *(const float4*)&noise[n * 64 + seg * 8];
    float4 n1 = *(const float4*)&noise[n * 64 + seg * 8 + 4];
    float k0 = g_key[n], k1 = g_key[NROWS + n];
    float i0 = g_kidx[n], i1 = g_kidx[NROWS + n];

    // load z tile: 64 d x 32 hw, coalesced over hw
    {
        const float* zb = z + (size_t)b * 65536 + p * 32;
        int w = t & 31, db = t >> 5;
        #pragma unroll
        for (int it = 0; it < 8; ++it) {
            int d = it * 8 + db;
            zt[d][w] = zb[d * 1024 + w];
        }
    }
    __syncthreads();

    float nv[8] = {n0.x, n0.y, n0.z, n0.w, n1.x, n1.y, n1.z, n1.w};
    float zv[8];
    #pragma unroll
    for (int i = 0; i < 8; ++i) zv[i] = zt[seg * 8 + i][row];

    float s = 0.f, xs = 0.f;
    #pragma unroll
    for (int i = 0; i < 8; ++i) { s += nv[i] * nv[i]; xs += zv[i] * zv[i]; }
    s += __shfl_down_sync(0xffffffffu, s, 4, 8);
    xs += __shfl_down_sync(0xffffffffu, xs, 4, 8);
    s += __shfl_down_sync(0xffffffffu, s, 2, 8);
    xs += __shfl_down_sync(0xffffffffu, xs, 2, 8);
    s += __shfl_down_sync(0xffffffffu, s, 1, 8);
    xs += __shfl_down_sync(0xffffffffu, xs, 1, 8);
    float norm2 = __shfl_sync(0xffffffffu, s, 0, 8);
    float x2 = __shfl_sync(0xffffffffu, xs, 0, 8);

    // merge the two code-half candidates (half0 wins ties: lower idx)
    float mk, mi;
    if (k1 < k0) { mk = k1; mi = i1; }
    else         { mk = k0; mi = i0; }
    if (seg == 0) out_ind[n] = mi;

    float dmin = x2 + mk;
    float scale = sqrtf(fmaxf(dmin, 0.f)) / fmaxf(sqrtf(norm2), 1e-9f);

    float part = 0.f;
    #pragma unroll
    for (int i = 0; i < 8; ++i) {
        float q = zv[i] + nv[i] * scale;
        part += q;
        zq[row * 65 + seg * 8 + i] = q;
    }
    sred[t] = part;
    __syncthreads();

    // two independent 128-thread tree reductions (rows 0-15 | rows 16-31)
    for (int off = 64; off > 0; off >>= 1) {
        if ((t & 127) < off) sred[t] += sred[t + off];
        __syncthreads();
    }
    // deterministic fixed-point accumulation of s^2 (scale 2^22)
    if ((t & 127) == 0) {
        float sv = sred[t];
        unsigned long long q =
            (unsigned long long)__double2ll_rn((double)sv * (double)sv * 4194304.0);
        atomicAdd(&g_lacc, q);
    }

    // write out transposed: out[b*65536 + dd*1024 + p*32 + r]
    {
        int dd = t >> 2;
        int rg = t & 3;
        float4 o0, o1;
        o0.x = zq[(rg * 8 + 0) * 65 + dd];
        o0.y = zq[(rg * 8 + 1) * 65 + dd];
        o0.z = zq[(rg * 8 + 2) * 65 + dd];
        o0.w = zq[(rg * 8 + 3) * 65 + dd];
        o1.x = zq[(rg * 8 + 4) * 65 + dd];
        o1.y = zq[(rg * 8 + 5) * 65 + dd];
        o1.z = zq[(rg * 8 + 6) * 65 + dd];
        o1.w = zq[(rg * 8 + 7) * 65 + dd];
        float* op = out + (size_t)b * 65536 + dd * 1024 + p * 32 + rg * 8;
        *(float4*)op = o0;
        *(float4*)(op + 4) = o1;
    }

    // completion protocol: single-thread fence orders this CTA's lacc adds
    __syncthreads();
    if (t == 0) {
        __threadfence();
        int v = atomicAdd(&g_ctr, 1);
        if (v == (int)gridDim.x - 1) {
            unsigned long long tot = atomicAdd(&g_lacc, 0ull);
            *out_loss = (float)((double)tot * (1.0 / 4194304.0) * (1.0 / 33554432.0));
            g_lacc = 0ull;   // reset for next graph replay
            g_ctr = 0;
        }
    }
}

// ---------------------------------------------------------------------------
extern "C" void kernel_launch(void* const* d_in, const int* in_sizes, int n_in,
                              void* d_out, int out_size) {
    const float* z     = (const float*)d_in[0];
    const float* cb    = (const float*)d_in[1];
    const float* noise = (const float*)d_in[2];
    float* out      = (float*)d_out;
    float* out_loss = out + ZQ_ELEMS;
    float* out_ind  = out + ZQ_ELEMS + 1;

    cudaFuncSetAttribute(gemm_argmin_kernel,
                         cudaFuncAttributeMaxDynamicSharedMemorySize, GEMM_SMEM);

    bprep_kernel<<<128, 256>>>(cb);
    gemm_argmin_kernel<<<148, 512, GEMM_SMEM>>>(z);
    zq_kernel<<<1024, 256>>>(z, noise, out, out_ind, out_loss);
}

// round 16
// speedup vs baseline: 1.4483x; 1.3641x over previous
#include <cuda_runtime.h>
#include <cuda_fp16.h>
#include <math.h>
#include <stdint.h>

// Problem constants
#define NROWS 32768   // B*H*W
#define DDIM  64
#define MCODE 1024
#define HWSZ  1024
#define ZQ_ELEMS 2097152

// Static device scratch
__device__ float g_key[2 * NROWS];       // per code-half: min key (y2 - 2*dot)
__device__ float g_kidx[2 * NROWS];      // per code-half: argmin index (as float)
__device__ float g_y2[MCODE];
__device__ unsigned long long g_lacc = 0ull;  // fixed-point sum of s^2 (scale 2^22)
__device__ int   g_ctr = 0;              // zq completion counter (self-resetting)
// Codebook packed fp16 hi/lo fragment order:
// [chunk(16)][s(4)][ci(64)][tt(4)] uint4 = { h2(k0,k0+1), h2(k0+8,k0+9),
//                                            l2(k0,k0+1), l2(k0+8,k0+9) },
// k0 = 16*s + 2*tt.  16KB per 64-code chunk.
__device__ uint4 g_bpack[16 * 1024];

// ---------------------------------------------------------------------------
// helpers
// ---------------------------------------------------------------------------
__device__ __forceinline__ uint32_t h2u(__half2 h) {
    return *reinterpret_cast<uint32_t*>(&h);
}
// split two floats into fp16 hi pair + fp16 lo (residual) pair
__device__ __forceinline__ void split2(float a, float b, uint32_t& hi, uint32_t& lo) {
    __half2 h = __floats2half2_rn(a, b);
    float2 f = __half22float2(h);
    __half2 l = __floats2half2_rn(a - f.x, b - f.y);
    hi = h2u(h); lo = h2u(l);
}
__device__ __forceinline__ uint32_t smem_u32(const void* p) {
    uint32_t a;
    asm("{ .reg .u64 t; cvta.to.shared.u64 t, %1; cvt.u32.u64 %0, t; }"
        : "=r"(a) : "l"(p));
    return a;
}
__device__ __forceinline__ void bulk_g2s(uint32_t dst, const void* src,
                                         uint32_t bytes, uint32_t mbar) {
    asm volatile(
        "cp.async.bulk.shared::cta.global.mbarrier::complete_tx::bytes [%0], [%1], %2, [%3];"
        :: "r"(dst), "l"(src), "r"(bytes), "r"(mbar) : "memory");
}
__device__ __forceinline__ void mbar_init(uint32_t mbar, uint32_t cnt) {
    asm volatile("mbarrier.init.shared.b64 [%0], %1;" :: "r"(mbar), "r"(cnt) : "memory");
}
__device__ __forceinline__ void mbar_expect_tx(uint32_t mbar, uint32_t bytes) {
    asm volatile("mbarrier.arrive.expect_tx.shared.b64 _, [%0], %1;"
                 :: "r"(mbar), "r"(bytes) : "memory");
}
__device__ __forceinline__ void mbar_wait(uint32_t mbar, uint32_t parity) {
    uint32_t done;
    asm volatile(
        "{\n\t.reg .pred p;\n\t"
        "mbarrier.try_wait.parity.acquire.cta.shared::cta.b64 p, [%1], %2;\n\t"
        "selp.b32 %0, 1, 0, p;\n\t}"
        : "=r"(done) : "r"(mbar), "r"(parity) : "memory");
    while (!done) {
        asm volatile(
            "{\n\t.reg .pred p;\n\t"
            "mbarrier.try_wait.parity.acquire.cta.shared::cta.b64 p, [%1], %2, 0x989680;\n\t"
            "selp.b32 %0, 1, 0, p;\n\t}"
            : "=r"(done) : "r"(mbar), "r"(parity) : "memory");
    }
}
// D(16x8) += A(16x16) * B(16x8), fp16 inputs, fp32 accum
__device__ __forceinline__ void mma16n8k16(float* c, uint32_t a0, uint32_t a1,
                                           uint32_t a2, uint32_t a3,
                                           uint32_t b0, uint32_t b1) {
    asm volatile(
        "mma.sync.aligned.m16n8k16.row.col.f32.f16.f16.f32 "
        "{%0,%1,%2,%3}, {%4,%5,%6,%7}, {%8,%9}, {%0,%1,%2,%3};"
        : "+f"(c[0]), "+f"(c[1]), "+f"(c[2]), "+f"(c[3])
        : "r"(a0), "r"(a1), "r"(a2), "r"(a3), "r"(b0), "r"(b1));
}

// ---------------------------------------------------------------------------
// Kernel 1: pack codebook into fp16 hi/lo fragment order + per-code y2.
// One thread per (code, s, tt): 1024*4*4 = 16384 threads.
// ---------------------------------------------------------------------------
__global__ void bprep_kernel(const float* __restrict__ cb) {
    int g = blockIdx.x * 256 + threadIdx.x;
    int c = g >> 4, s = (g >> 2) & 3, tt = g & 3;
    int k0 = 16 * s + 2 * tt;
    float v0 = cb[c * DDIM + k0];
    float v1 = cb[c * DDIM + k0 + 1];
    float v8 = cb[c * DDIM + k0 + 8];
    float v9 = cb[c * DDIM + k0 + 9];
    uint32_t h01, l01, h89, l89;
    split2(v0, v1, h01, l01);
    split2(v8, v9, h89, l89);
    int chunk = c >> 6, ci = c & 63;
    g_bpack[chunk * 1024 + s * 256 + ci * 4 + tt] = make_uint4(h01, h89, l01, l89);
    // y2: 16 threads cover one code's 64 dims (4 each); width-16 tree
    float y = v0 * v0 + v1 * v1 + v8 * v8 + v9 * v9;
    y += __shfl_down_sync(0xffffffffu, y, 8, 16);
    y += __shfl_down_sync(0xffffffffu, y, 4, 16);
    y += __shfl_down_sync(0xffffffffu, y, 2, 16);
    y += __shfl_down_sync(0xffffffffu, y, 1, 16);
    if ((g & 15) == 0) g_y2[c] = y;
}

// ---------------------------------------------------------------------------
// Kernel 2: 3xFP16 m16n8k16 distance GEMM + fused argmin.
// Grid 148 = 74 uneven row blocks (12x416 + 62x448) x 2 code halves.
// 512 threads = 16 warps x 32 rows; 8 chunks of 64 codes, B double-buffered
// (16KB chunks). A converted once to fp16 hi/lo uint4 [s(4)][row(512)][tt(4)].
// ---------------------------------------------------------------------------
#define SM_MB   0
#define SM_Y2   128
#define SM_A    2176
#define SM_B    133248                   // SM_A + 4*512*4*16 = 131072
#define GEMM_SMEM (133248 + 2 * 16384)   // 166016

__global__ __launch_bounds__(512, 1)
void gemm_argmin_kernel(const float* __restrict__ z) {
    extern __shared__ char sm[];
    uint32_t sb = smem_u32(sm);
    uint4* A4 = (uint4*)(sm + SM_A);
    const float* y2s = (const float*)(sm + SM_Y2);
    int tid = threadIdx.x;
    int wid = tid >> 5, lane = tid & 31;
    int g = lane >> 2, tt = lane & 3;
    int half = blockIdx.x & 1;
    int bi = blockIdx.x >> 1;            // 0..73
    int r0, rows;
    if (bi < 12) { r0 = bi * 416;               rows = 416; }
    else         { r0 = 4992 + (bi - 12) * 448; rows = 448; }
    int w32 = wid * 32;
    bool active = (w32 < rows);
    const uint4* bsrc = g_bpack + half * 8 * 1024;

    if (tid == 0) {
        mbar_init(sb + SM_MB + 0, 1);
        mbar_init(sb + SM_MB + 8, 1);
    }
    __syncthreads();  // make mbar init visible before bulk ops

    // kick off B chunks 0 and 1 (16KB each)
    if (tid == 0) {
        mbar_expect_tx(sb + SM_MB + 0, 16384);
        bulk_g2s(sb + SM_B, bsrc, 16384, sb + SM_MB + 0);
        mbar_expect_tx(sb + SM_MB + 8, 16384);
        bulk_g2s(sb + SM_B + 16384, bsrc + 1024, 16384, sb + SM_MB + 8);
    }

    // A prep: z -> fp16 hi/lo fragment uint4s. Per-row (b,hw) addressing.
    {
        int roff = lane >> 2, tp = lane & 3;
        #pragma unroll
        for (int p = 0; p < 4; ++p) {
            int r = p * 128 + wid * 8 + roff;
            if (r < rows) {
                int n = r0 + r;
                const float* zp = z + (size_t)(n >> 10) * 65536 + (n & 1023);
                #pragma unroll
                for (int s = 0; s < 4; ++s) {
                    int k0 = 16 * s + 2 * tp;
                    float v0 = zp[k0 * 1024];
                    float v1 = zp[(k0 + 1) * 1024];
                    float v8 = zp[(k0 + 8) * 1024];
                    float v9 = zp[(k0 + 9) * 1024];
                    uint32_t h01, l01, h89, l89;
                    split2(v0, v1, h01, l01);
                    split2(v8, v9, h89, l89);
                    A4[(s * 512 + r) * 4 + tp] = make_uint4(h01, h89, l01, l89);
                }
            }
        }
    }
    for (int i = tid; i < 512; i += 512)
        ((float*)(sm + SM_Y2))[i] = g_y2[half * 512 + i];
    __syncthreads();

    float best[4];
    int   bidx[4];
    #pragma unroll
    for (int i = 0; i < 4; ++i) { best[i] = 3.4028235e38f; bidx[i] = 0; }

    for (int ch = 0; ch < 8; ++ch) {
        int buf = ch & 1;
        mbar_wait(sb + SM_MB + buf * 8, (ch >> 1) & 1);

        if (active) {
            const uint4* Bb = (const uint4*)(sm + SM_B + buf * 16384);

            float acc[2][8][4];
            #pragma unroll
            for (int m = 0; m < 2; ++m)
                #pragma unroll
                for (int j = 0; j < 8; ++j)
                    #pragma unroll
                    for (int e = 0; e < 4; ++e) acc[m][j][e] = 0.f;

            #pragma unroll
            for (int s = 0; s < 4; ++s) {
                // per-row uint4: .x = h(k0,k0+1), .y = h(k0+8,k0+9), .z/.w = lo
                uint4 ra = A4[(s * 512 + w32 + g) * 4 + tt];       // row g
                uint4 rb = A4[(s * 512 + w32 + 8 + g) * 4 + tt];   // row g+8
                uint4 rc = A4[(s * 512 + w32 + 16 + g) * 4 + tt];  // row g+16
                uint4 rd = A4[(s * 512 + w32 + 24 + g) * 4 + tt];  // row g+24
                #pragma unroll
                for (int j = 0; j < 8; ++j) {
                    uint4 bq = Bb[s * 256 + (j * 8 + g) * 4 + tt]; // {bh01,bh89,bl01,bl89}
                    // m-tile 0 (rows w32..w32+15): A frag = {ra.x, rb.x, ra.y, rb.y}
                    mma16n8k16(acc[0][j], ra.x, rb.x, ra.y, rb.y, bq.x, bq.y); // hi*hi
                    mma16n8k16(acc[0][j], ra.x, rb.x, ra.y, rb.y, bq.z, bq.w); // hi*lo
                    mma16n8k16(acc[0][j], ra.z, rb.z, ra.w, rb.w, bq.x, bq.y); // lo*hi
                    // m-tile 1 (rows w32+16..w32+31)
                    mma16n8k16(acc[1][j], rc.x, rd.x, rc.y, rd.y, bq.x, bq.y);
                    mma16n8k16(acc[1][j], rc.x, rd.x, rc.y, rd.y, bq.z, bq.w);
                    mma16n8k16(acc[1][j], rc.z, rd.z, rc.w, rd.w, bq.x, bq.y);
                }
            }

            // epilogue: key = y2 - 2*dot, running argmin (first-occurrence ties)
            #pragma unroll
            for (int j = 0; j < 8; ++j) {
                int cl = ch * 64 + j * 8 + 2 * tt;
                float2 y = ((const float2*)y2s)[cl >> 1];
                #pragma unroll
                for (int m = 0; m < 2; ++m) {
                    float k0 = fmaf(acc[m][j][0], -2.0f, y.x);
                    float k1 = fmaf(acc[m][j][1], -2.0f, y.y);
                    float k2 = fmaf(acc[m][j][2], -2.0f, y.x);
                    float k3 = fmaf(acc[m][j][3], -2.0f, y.y);
                    if (k0 < best[m * 2 + 0]) { best[m * 2 + 0] = k0; bidx[m * 2 + 0] = cl; }
                    if (k1 < best[m * 2 + 0]) { best[m * 2 + 0] = k1; bidx[m * 2 + 0] = cl + 1; }
                    if (k2 < best[m * 2 + 1]) { best[m * 2 + 1] = k2; bidx[m * 2 + 1] = cl; }
                    if (k3 < best[m * 2 + 1]) { best[m * 2 + 1] = k3; bidx[m * 2 + 1] = cl + 1; }
                }
            }
        }

        __syncthreads();  // everyone done with buf before refill
        if (ch + 2 < 8 && tid == 0) {
            mbar_expect_tx(sb + SM_MB + buf * 8, 16384);
            bulk_g2s(sb + SM_B + buf * 16384, bsrc + (ch + 2) * 1024, 16384,
                     sb + SM_MB + buf * 8);
        }
    }

    // cross-lane (t-group) argmin reduce; lane with tt==0 owns the row
    if (active) {
        #pragma unroll
        for (int m = 0; m < 4; ++m) {
            float v = best[m];
            int id = bidx[m];
            #pragma unroll
            for (int d = 1; d < 4; d <<= 1) {
                float v2 = __shfl_xor_sync(0xffffffffu, v, d);
                int   i2 = __shfl_xor_sync(0xffffffffu, id, d);
                if (v2 < v || (v2 == v && i2 < id)) { v = v2; id = i2; }
            }
            if (tt == 0) {
                int row = r0 + w32 + (m >> 1) * 16 + (m & 1) * 8 + g;
                g_key[half * NROWS + row] = v;
                g_kidx[half * NROWS + row] = (float)(half * 512 + id);
            }
        }
    }
}

// ---------------------------------------------------------------------------
// Kernel 3: z_q, output transpose, ind merge + deterministic fixed-point
// loss accumulation. Last CTA finalizes + resets counters. (Unchanged R15.)
// ---------------------------------------------------------------------------
__global__ __launch_bounds__(256)
void zq_kernel(const float* __restrict__ z,
               const float* __restrict__ noise,
               float* __restrict__ out,
               float* __restrict__ out_ind,
               float* __restrict__ out_loss) {
    __shared__ float zt[64][33];     // z[b, d, hw0+w] tile
    __shared__ float zq[32 * 65];
    __shared__ float sred[256];
    int t = threadIdx.x;
    int c = blockIdx.x;
    int b = c >> 5;
    int p = c & 31;
    int r0 = b * 1024 + p * 32;

    int row = t >> 3;
    int seg = t & 7;
    int n = r0 + row;

    // hoisted independent loads (issue before the tile barrier)
    float4 n0 = *(const float4*)&noise[n * 64 + seg * 8];
    float4 n1 = *(const float4*)&noise[n * 64 + seg * 8 + 4];
    float k0 = g_key[n], k1 = g_key[NROWS + n];
    float i0 = g_kidx[n], i1 = g_kidx[NROWS + n];

    // load z tile: 64 d x 32 hw, coalesced over hw
    {
        const float* zb = z + (size_t)b * 65536 + p * 32;
        int w = t & 31, db = t >> 5;
        #pragma unroll
        for (int it = 0; it < 8; ++it) {
            int d = it * 8 + db;
            zt[d][w] = zb[d * 1024 + w];
        }
    }
    __syncthreads();

    float nv[8] = {n0.x, n0.y, n0.z, n0.w, n1.x, n1.y, n1.z, n1.w};
    float zv[8];
    #pragma unroll
    for (int i = 0; i < 8; ++i) zv[i] = zt[seg * 8 + i][row];

    float s = 0.f, xs = 0.f;
    #pragma unroll
    for (int i = 0; i < 8; ++i) { s += nv[i] * nv[i]; xs += zv[i] * zv[i]; }
    s += __shfl_down_sync(0xffffffffu, s, 4, 8);
    xs += __shfl_down_sync(0xffffffffu, xs, 4, 8);
    s += __shfl_down_sync(0xffffffffu, s, 2, 8);
    xs += __shfl_down_sync(0xffffffffu, xs, 2, 8);
    s += __shfl_down_sync(0xffffffffu, s, 1, 8);
    xs += __shfl_down_sync(0xffffffffu, xs, 1, 8);
    float norm2 = __shfl_sync(0xffffffffu, s, 0, 8);
    float x2 = __shfl_sync(0xffffffffu, xs, 0, 8);

    // merge the two code-half candidates (half0 wins ties: lower idx)
    float mk, mi;
    if (k1 < k0) { mk = k1; mi = i1; }
    else         { mk = k0; mi = i0; }
    if (seg == 0) out_ind[n] = mi;

    float dmin = x2 + mk;
    float scale = sqrtf(fmaxf(dmin, 0.f)) / fmaxf(sqrtf(norm2), 1e-9f);

    float part = 0.f;
    #pragma unroll
    for (int i = 0; i < 8; ++i) {
        float q = zv[i] + nv[i] * scale;
        part += q;
        zq[row * 65 + seg * 8 + i] = q;
    }
    sred[t] = part;
    __syncthreads();

    // two independent 128-thread tree reductions (rows 0-15 | rows 16-31)
    for (int off = 64; off > 0; off >>= 1) {
        if ((t & 127) < off) sred[t] += sred[t + off];
        __syncthreads();
    }
    // deterministic fixed-point accumulation of s^2 (scale 2^22)
    if ((t & 127) == 0) {
        float sv = sred[t];
        unsigned long long q =
            (unsigned long long)__double2ll_rn((double)sv * (double)sv * 4194304.0);
        atomicAdd(&g_lacc, q);
    }

    // write out transposed: out[b*65536 + dd*1024 + p*32 + r]
    {
        int dd = t >> 2;
        int rg = t & 3;
        float4 o0, o1;
        o0.x = zq[(rg * 8 + 0) * 65 + dd];
        o0.y = zq[(rg * 8 + 1) * 65 + dd];
        o0.z = zq[(rg * 8 + 2) * 65 + dd];
        o0.w = zq[(rg * 8 + 3) * 65 + dd];
        o1.x = zq[(rg * 8 + 4) * 65 + dd];
        o1.y = zq[(rg * 8 + 5) * 65 + dd];
        o1.z = zq[(rg * 8 + 6) * 65 + dd];
        o1.w = zq[(rg * 8 + 7) * 65 + dd];
        float* op = out + (size_t)b * 65536 + dd * 1024 + p * 32 + rg * 8;
        *(float4*)op = o0;
        *(float4*)(op + 4) = o1;
    }

    // completion protocol: single-thread fence orders this CTA's lacc adds
    __syncthreads();
    if (t == 0) {
        __threadfence();
        int v = atomicAdd(&g_ctr, 1);
        if (v == (int)gridDim.x - 1) {
            unsigned long long tot = atomicAdd(&g_lacc, 0ull);
            *out_loss = (float)((double)tot * (1.0 / 4194304.0) * (1.0 / 33554432.0));
            g_lacc = 0ull;   // reset for next graph replay
            g_ctr = 0;
        }
    }
}

// ---------------------------------------------------------------------------
extern "C" void kernel_launch(void* const* d_in, const int* in_sizes, int n_in,
                              void* d_out, int out_size) {
    const float* z     = (const float*)d_in[0];
    const float* cb    = (const float*)d_in[1];
    const float* noise = (const float*)d_in[2];
    float* out      = (float*)d_out;
    float* out_loss = out + ZQ_ELEMS;
    float* out_ind  = out + ZQ_ELEMS + 1;

    cudaFuncSetAttribute(gemm_argmin_kernel,
                         cudaFuncAttributeMaxDynamicSharedMemorySize, GEMM_SMEM);

    bprep_kernel<<<64, 256>>>(cb);
    gemm_argmin_kernel<<<148, 512, GEMM_SMEM>>>(z);
    zq_kernel<<<1024, 256>>>(z, noise, out, out_ind, out_loss);
}